// round 6
// baseline (speedup 1.0000x reference)
#include <cuda_runtime.h>
#include <cstdint>

#define NMAX   500000
#define HBITS  21
#define HSIZE  (1u << HBITS)
#define HMASK  (HSIZE - 1u)
#define EMPTYK 0xFFFFFFFFu
#define TPM    256
#define PPW    8      // points per warp iteration in k_mlp

typedef unsigned long long ull;

// ---------------- device scratch ----------------
__device__ uint32_t g_keys[3][HSIZE];
__device__ int      g_vals[3][HSIZE];
__device__ int      g_counter[3];
__device__ int      g_pt2vox[3][NMAX];
__device__ float    g_sums[3][NMAX * 64];
__device__ int      g_counts[3][NMAX];
__device__ int      g_ptidx[3][NMAX];
__device__ float    g_ms[3][NMAX * 64];

__device__ __forceinline__ uint32_t hash32(uint32_t x) {
    x ^= x >> 16; x *= 0x85ebca6bu;
    x ^= x >> 13; x *= 0xc2b2ae35u;
    x ^= x >> 16;
    return x;
}

__device__ __forceinline__ ull fma2(ull a, ull b, ull c) {
    ull d;
    asm("fma.rn.f32x2 %0, %1, %2, %3;" : "=l"(d) : "l"(a), "l"(b), "l"(c));
    return d;
}
__device__ __forceinline__ float2 unpack2(ull v) {
    float2 r;
    asm("mov.b64 {%0, %1}, %2;" : "=f"(r.x), "=f"(r.y) : "l"(v));
    return r;
}

// ---------------- K1: clear all 3 hash tables + sums/counts ----------------
__global__ void k_clear(int n) {
    int tid = blockIdx.x * blockDim.x + threadIdx.x;
    int stride = gridDim.x * blockDim.x;
    int m4 = n * 16;
    float4 z = make_float4(0.f, 0.f, 0.f, 0.f);
#pragma unroll
    for (int s = 0; s < 3; s++) {
        float4* s4 = reinterpret_cast<float4*>(&g_sums[s][0]);
        for (int i = tid; i < m4; i += stride) s4[i] = z;
    }
    for (int i = tid; i < (int)HSIZE; i += stride) {
        g_keys[0][i] = EMPTYK; g_keys[1][i] = EMPTYK; g_keys[2][i] = EMPTYK;
        g_vals[0][i] = -1;     g_vals[1][i] = -1;     g_vals[2][i] = -1;
    }
    for (int i = tid; i < n; i += stride) {
        g_counts[0][i] = 0; g_counts[1][i] = 0; g_counts[2][i] = 0;
    }
    if (tid == 0) { g_counter[0] = 0; g_counter[1] = 0; g_counter[2] = 0; }
}

// ---------------- K2: hash-insert (all scales via blockIdx.y) ----------------
__global__ void k_insert(const int* __restrict__ coords, int n) {
    int i = blockIdx.x * blockDim.x + threadIdx.x;
    if (i >= n) return;
    int si = blockIdx.y;
    int shift = si + 1;
    int4 cd = reinterpret_cast<const int4*>(coords)[i];
    int vx = cd.x >> shift, vy = cd.y >> shift, vz = cd.z >> shift;
    uint32_t key = (uint32_t)((((cd.w * 512) + vx) * 512 + vy) * 512 + vz);
    uint32_t slot = hash32(key) & HMASK;
    int id = -1;
#pragma unroll 1
    while (true) {
        uint32_t old = atomicCAS(&g_keys[si][slot], EMPTYK, key);
        if (old == EMPTYK) {
            id = atomicAdd(&g_counter[si], 1);
            atomicExch(&g_vals[si][slot], id);
            break;
        }
        if (old == key) {
            volatile int* vp = (volatile int*)&g_vals[si][slot];
#pragma unroll 1
            while ((id = *vp) < 0) { __nanosleep(40); }
            break;
        }
        slot = (slot + 1) & HMASK;
    }
    g_pt2vox[si][i] = id;
    atomicAdd(&g_counts[si][id], 1);
}

// ---------------- K3: per-voxel feature sums (all 3 scales, one feats read) ----------------
__global__ void k_accum(const float* __restrict__ feats, int n) {
    int tid = blockIdx.x * blockDim.x + threadIdx.x;
    if (tid >= n * 16) return;
    int p = tid >> 4, q = tid & 15;
    float4 v = reinterpret_cast<const float4*>(feats)[tid];
#pragma unroll
    for (int si = 0; si < 3; si++) {
        int vid = g_pt2vox[si][p];
        float* dst = &g_sums[si][(size_t)vid * 64 + q * 4];
        asm volatile("red.global.add.v4.f32 [%0], {%1, %2, %3, %4};"
                     :: "l"(dst), "f"(v.x), "f"(v.y), "f"(v.z), "f"(v.w)
                     : "memory");
    }
}

// ---------------- K4: 8-corner probe + exact trilinear argmax ----------------
__device__ __forceinline__ int hlookup(int si, uint32_t key) {
    uint32_t slot = hash32(key) & HMASK;
#pragma unroll 1
    while (true) {
        uint32_t k = g_keys[si][slot];
        if (k == key) return g_vals[si][slot];
        if (k == EMPTYK) return -1;
        slot = (slot + 1) & HMASK;
    }
}

__global__ void k_select(const int* __restrict__ coords, int n) {
    int i = blockIdx.x * blockDim.x + threadIdx.x;
    if (i >= n) return;
    int si = blockIdx.y;
    int shift = si + 1;
    int4 cd = reinterpret_cast<const int4*>(coords)[i];
    int scale = 1 << shift;
    float invs = 1.0f / (float)scale;
    int vx = cd.x >> shift, vy = cd.y >> shift, vz = cd.z >> shift;
    float fx = (float)(cd.x - (vx << shift)) * invs;   // exact binary fractions
    float fy = (float)(cd.y - (vy << shift)) * invs;
    float fz = (float)(cd.z - (vz << shift)) * invs;
    float gx = 1.0f - fx, gy = 1.0f - fy, gz = 1.0f - fz;

    float bestw = -1.0f;
    int bestid = 0;
#pragma unroll
    for (int j = 0; j < 8; j++) {
        int bx = (j >> 2) & 1, by = (j >> 1) & 1, bz = j & 1;
        float w = (bx ? fx : gx) * (by ? fy : gy) * (bz ? fz : gz);  // exact
        uint32_t key = (uint32_t)((((cd.w * 512) + (vx + bx)) * 512 + (vy + by)) * 512 + (vz + bz));
        int id = hlookup(si, key);
        float val = (id >= 0) ? w : 0.0f;
        if (val > bestw) { bestw = val; bestid = id; }  // first-max == jnp.argmax
    }
    g_ptidx[si][i] = bestid;
}

// ---------------- K5: per-scale residual MLP (warp-independent, 8 pts/warp) ----------------
// Weights per scale packed in smem as k-pair ulls, row stride 66 ull
// (conflict-free phased LDS.128). Activations per warp in smem, read via
// warp-uniform broadcast LDS.128 (1 wavefront each). h overwrites res in place.
#define WPK_ULL   (2 * 32 * 66)                    // 4224 ull = 33792 B
#define ACT_OFF_F (WPK_ULL * 2)                    // float index of act region
#define SMEM_MLP  (WPK_ULL * 8 + 8 * (PPW * 64) * 4)   // 33792 + 16384 = 50176 B

__global__ __launch_bounds__(TPM, 2) void k_mlp(
    const float* __restrict__ feats,
    const float* __restrict__ W1g, const float* __restrict__ b1g,
    const float* __restrict__ W2g, const float* __restrict__ b2g,
    int n)
{
    extern __shared__ ull smu[];
    float* smf = (float*)smu;
    const int s    = blockIdx.y;
    const int bs   = blockIdx.x;
    const int nb   = gridDim.x;
    const int warp = threadIdx.x >> 5;
    const int lane = threadIdx.x & 31;
    const int c0   = lane * 2;

    // ---- stage + k-pair-pack this scale's weights ----
    for (int j = threadIdx.x; j < 8192; j += TPM) {
        int layer = j >> 12, r = j & 4095;
        int k = r >> 6, c = r & 63;
        float v = (layer ? W2g : W1g)[s * 4096 + r];
        smf[(((layer * 32 + (c >> 1)) * 66) + ((k >> 1) << 1) + (c & 1)) * 2 + (k & 1)] = v;
    }
    const float b1x = b1g[s * 64 + c0], b1y = b1g[s * 64 + c0 + 1];
    const float b2x = b2g[s * 64 + c0], b2y = b2g[s * 64 + c0 + 1];
    __syncthreads();

    const ull* w0b = smu + lane * 66;          // layer-1 weight row for this lane
    const ull* w1b = smu + 2112 + lane * 66;   // layer-2
    float* actw = smf + ACT_OFF_F + warp * (PPW * 64);   // [PPW][64], res then h

    const int tiles = (n + PPW - 1) / PPW;

#define GEMV(WB) do {                                                          \
    _Pragma("unroll") for (int p = 0; p < PPW; p++) { a0[p] = 0ull; a1[p] = 0ull; } \
    _Pragma("unroll")                                                          \
    for (int kc = 0; kc < 16; kc++) {                                          \
        ulonglong2 wA = *(const ulonglong2*)&(WB)[4 * kc];                     \
        ulonglong2 wB_ = *(const ulonglong2*)&(WB)[4 * kc + 2];                \
        _Pragma("unroll")                                                      \
        for (int p = 0; p < PPW; p++) {                                        \
            ulonglong2 av = *(const ulonglong2*)&((const ull*)actw)[p * 32 + 2 * kc]; \
            a0[p] = fma2(av.x, wA.x, a0[p]);                                   \
            a1[p] = fma2(av.x, wA.y, a1[p]);                                   \
            a0[p] = fma2(av.y, wB_.x, a0[p]);                                  \
            a1[p] = fma2(av.y, wB_.y, a1[p]);                                  \
        }                                                                      \
    }                                                                          \
} while (0)

    for (int t = bs * 8 + warp; t < tiles; t += nb * 8) {
        const int i0 = t * PPW;
        float2 pf[PPW];

        // ---- gather voxel mean + residual (coalesced 256B rows) ----
#pragma unroll
        for (int p = 0; p < PPW; p++) {
            int i = i0 + p; if (i >= n) i = n - 1;
            int idx = g_ptidx[s][i];
            float inv = 1.0f / (float)g_counts[s][idx];
            float2 sv = *(const float2*)&g_sums[s][(size_t)idx * 64 + c0];
            float2 f2 = *(const float2*)&feats[(size_t)i * 64 + c0];
            pf[p] = f2;
            *(float2*)&actw[p * 64 + c0] = make_float2(f2.x - sv.x * inv,
                                                       f2.y - sv.y * inv);
        }
        __syncwarp();

        ull a0[PPW], a1[PPW];
        // ---- GEMV1: h = relu(res @ W1 + b1) * feats ----
        GEMV(w0b);
        __syncwarp();   // all lanes done reading res before h overwrites
#pragma unroll
        for (int p = 0; p < PPW; p++) {
            float2 u0 = unpack2(a0[p]);
            float2 u1 = unpack2(a1[p]);
            float h0 = fmaxf(u0.x + u0.y + b1x, 0.0f) * pf[p].x;
            float h1 = fmaxf(u1.x + u1.y + b1y, 0.0f) * pf[p].y;
            *(float2*)&actw[p * 64 + c0] = make_float2(h0, h1);
        }
        __syncwarp();

        // ---- GEMV2: ms = relu(h @ W2 + b2) ----
        GEMV(w1b);
#pragma unroll
        for (int p = 0; p < PPW; p++) {
            if (i0 + p < n) {
                float2 u0 = unpack2(a0[p]);
                float2 u1 = unpack2(a1[p]);
                float m0 = fmaxf(u0.x + u0.y + b2x, 0.0f);
                float m1 = fmaxf(u1.x + u1.y + b2y, 0.0f);
                *(float2*)&g_ms[s][(size_t)(i0 + p) * 64 + c0] = make_float2(m0, m1);
            }
        }
        __syncwarp();   // protect actw WAR for next iteration
    }
#undef GEMV
}

// ---------------- K6: attention + combine (streaming) ----------------
__global__ __launch_bounds__(256) void k_att(
    const float* __restrict__ Wag, const float* __restrict__ bag,
    float* __restrict__ out, int n)
{
    int warp = threadIdx.x >> 5, lane = threadIdx.x & 31;
    int i = blockIdx.x * 8 + warp;
    if (i >= n) return;
    int c0 = lane * 2;

    float2 m0 = *(const float2*)&g_ms[0][(size_t)i * 64 + c0];
    float2 m1 = *(const float2*)&g_ms[1][(size_t)i * 64 + c0];
    float2 m2 = *(const float2*)&g_ms[2][(size_t)i * 64 + c0];
    float ssx = m0.x + m1.x + m2.x;
    float ssy = m0.y + m1.y + m2.y;

    float2 wa0 = *(const float2*)&Wag[c0];
    float2 wa1 = *(const float2*)&Wag[64 + c0];
    float2 wa2 = *(const float2*)&Wag[128 + c0];
    float p0 = ssx * wa0.x + ssy * wa0.y;
    float p1 = ssx * wa1.x + ssy * wa1.y;
    float p2 = ssx * wa2.x + ssy * wa2.y;
#pragma unroll
    for (int off = 16; off; off >>= 1) {
        p0 += __shfl_xor_sync(0xffffffffu, p0, off);
        p1 += __shfl_xor_sync(0xffffffffu, p1, off);
        p2 += __shfl_xor_sync(0xffffffffu, p2, off);
    }
    float a0 = 1.0f / (1.0f + expf(-(p0 + bag[0])));
    float a1 = 1.0f / (1.0f + expf(-(p1 + bag[1])));
    float a2 = 1.0f / (1.0f + expf(-(p2 + bag[2])));

    float2 o;
    o.x = m0.x * a0 + m1.x * a1 + m2.x * a2;
    o.y = m0.y * a0 + m1.y * a1 + m2.y * a2;
    *(float2*)&out[(size_t)i * 64 + c0] = o;
}

// ---------------- host launcher ----------------
extern "C" void kernel_launch(void* const* d_in, const int* in_sizes, int n_in,
                              void* d_out, int out_size) {
    const float* feats = (const float*)d_in[0];
    const int*   coords = (const int*)d_in[1];
    const float* W1 = (const float*)d_in[2];
    const float* b1 = (const float*)d_in[3];
    const float* W2 = (const float*)d_in[4];
    const float* b2 = (const float*)d_in[5];
    const float* Wa = (const float*)d_in[6];
    const float* ba = (const float*)d_in[7];
    float* out = (float*)d_out;

    int n = in_sizes[1] / 4;   // coords is (N,4) int32
    if (n > NMAX) n = NMAX;

    k_clear<<<4096, 256>>>(n);
    dim3 gi((n + 255) / 256, 3);
    k_insert<<<gi, 256>>>(coords, n);
    k_accum<<<(n * 16 + 255) / 256, 256>>>(feats, n);
    k_select<<<gi, 256>>>(coords, n);

    int sms = 148;
    cudaDeviceGetAttribute(&sms, cudaDevAttrMultiProcessorCount, 0);
    cudaFuncSetAttribute(k_mlp, cudaFuncAttributeMaxDynamicSharedMemorySize, SMEM_MLP);
    dim3 gm(sms * 2, 3);   // 2 CTAs/SM (reg-limited), persistent over tiles
    k_mlp<<<gm, TPM, SMEM_MLP>>>(feats, W1, b1, W2, b2, n);

    k_att<<<(n + 7) / 8, 256>>>(Wa, ba, out, n);
}